// round 13
// baseline (speedup 1.0000x reference)
#include <cuda_runtime.h>
#include <cuda_fp16.h>
#include <cstdint>

// ---------------- configuration ----------------
#define TOK_TILE     16
#define NUM_TILES    1024         // 16384 / 16  -> ~7 CTAs resident per SM, 1.2% imbalance
#define THREADS      128          // 4 warps; each warp: 16 tokens x 16 cols (mt=1, nt=2)
#define KB_STEPS     8            // K=256 in blocks of 32
#define NCHUNKS      64
#define NSLICES      (KB_STEPS * NCHUNKS)   // 512
#define SLICE_WORDS  1024         // 64 o x 32 k halves = 1024 b32 words

// smem: only the x2 tile (16 rows x 68 floats)
#define X2_STRIDE    68
#define SMEM_BYTES   (TOK_TILE * X2_STRIDE * 4)   // 4352

// W pre-converted to fp16, fragment-ordered per (kb, c) slice
__device__ uint32_t g_Wh[4096 * 128];   // 2 MB

static __device__ __forceinline__ uint32_t pack_h2(float lo, float hi) {
    uint32_t r;
    asm("cvt.rn.f16x2.f32 %0, %1, %2;" : "=r"(r) : "f"(hi), "f"(lo));
    return r;
}
// f16-accumulator HMMA: D(2xf16x2) = A*B + C
static __device__ __forceinline__ void mma_h_init(uint32_t& d0, uint32_t& d1,
                                                  const uint32_t* a, uint32_t b0, uint32_t b1,
                                                  uint32_t c0, uint32_t c1) {
    asm("mma.sync.aligned.m16n8k16.row.col.f16.f16.f16.f16 "
        "{%0,%1}, {%2,%3,%4,%5}, {%6,%7}, {%8,%9};"
        : "=r"(d0), "=r"(d1)
        : "r"(a[0]), "r"(a[1]), "r"(a[2]), "r"(a[3]), "r"(b0), "r"(b1),
          "r"(c0), "r"(c1));
}
static __device__ __forceinline__ void mma_h_acc(uint32_t& d0, uint32_t& d1,
                                                 const uint32_t* a, uint32_t b0, uint32_t b1) {
    asm("mma.sync.aligned.m16n8k16.row.col.f16.f16.f16.f16 "
        "{%0,%1}, {%2,%3,%4,%5}, {%6,%7}, {%0,%1};"
        : "+r"(d0), "+r"(d1)
        : "r"(a[0]), "r"(a[1]), "r"(a[2]), "r"(a[3]), "r"(b0), "r"(b1));
}
static __device__ __forceinline__ float2 h2f2(uint32_t p) {
    __half2 h = *reinterpret_cast<__half2*>(&p);
    return __half22float2(h);
}

// -------- W pre-transform: fp32 -> f16x2, fragment order (unchanged) --------
__global__ void prep_kernel(const float* __restrict__ W) {
    int idx = blockIdx.x * 256 + threadIdx.x;      // 524,288 threads
    int s   = idx >> 10;
    int rem = idx & 1023;
    int o   = rem >> 4;
    int r   = (rem >> 2) & 3;
    int q   = rem & 3;
    int ks  = q >> 1, hb = q & 1;
    int kb  = s >> 6, c = s & 63;
    const float* src = W + (size_t)(c * 64 + o) * 256 + kb * 32 + ks * 16 + hb * 8 + r * 2;
    g_Wh[idx] = pack_h2(src[0], src[1]);
}

// this warp's B fragments for slice s: 1 LDG.128 per nt, fully coalesced
static __device__ __forceinline__ void load_frags(uint32_t bf[2][4], int s,
                                                  int cn, int gID, int tig) {
    const uint4* base = reinterpret_cast<const uint4*>(g_Wh) + (size_t)s * (SLICE_WORDS / 4);
#pragma unroll
    for (int nt = 0; nt < 2; nt++) {
        int o = cn + nt * 8 + gID;
        uint4 v = __ldg(base + o * 4 + tig);
        bf[nt][0] = v.x; bf[nt][1] = v.y; bf[nt][2] = v.z; bf[nt][3] = v.w;
    }
}

// A fragments (x1 -> fp16) for one k-block; mt=1 (16 tokens), reused across 64 chunks
static __device__ __forceinline__ void load_A(uint32_t A[2][4],
                                              const float* __restrict__ x1,
                                              int tok0, int kb, int gID, int tig) {
    const float* base = x1 + (size_t)tok0 * 256 + kb * 32;
    const float* r0 = base + (size_t)gID * 256;
    const float* r1 = r0 + 8 * 256;
#pragma unroll
    for (int ks = 0; ks < 2; ks++) {
        int k0 = ks * 16 + tig * 2;
        float2 a0 = *reinterpret_cast<const float2*>(r0 + k0);
        float2 a1 = *reinterpret_cast<const float2*>(r1 + k0);
        float2 a2 = *reinterpret_cast<const float2*>(r0 + k0 + 8);
        float2 a3 = *reinterpret_cast<const float2*>(r1 + k0 + 8);
        A[ks][0] = pack_h2(a0.x, a0.y);
        A[ks][1] = pack_h2(a1.x, a1.y);
        A[ks][2] = pack_h2(a2.x, a2.y);
        A[ks][3] = pack_h2(a3.x, a3.y);
    }
}

// one chunk: 4 HMMA (2nt x 2ks-chain) + fp32 epilogue
template <bool FIRST>
static __device__ __forceinline__ void chunk_mma(
    const uint32_t bf[2][4], const float* __restrict__ x2s,
    const float* __restrict__ bvec, const uint32_t A[2][4],
    float y[2][4], int c, int cn, int gID, int tig)
{
    float xv0 = x2s[gID * X2_STRIDE + c];
    float xv1 = x2s[(gID + 8) * X2_STRIDE + c];
#pragma unroll
    for (int nt = 0; nt < 2; nt++) {
        uint32_t cb = 0;   // f16x2 zero
        if (FIRST) {
            float2 bb = __ldg(reinterpret_cast<const float2*>(
                bvec + c * 64 + cn + nt * 8 + tig * 2));
            cb = pack_h2(bb.x, bb.y);
        }
        uint32_t d0, d1;
        mma_h_init(d0, d1, A[0], bf[nt][0], bf[nt][1], cb, cb);
        mma_h_acc (d0, d1, A[1], bf[nt][2], bf[nt][3]);
        float2 lo = h2f2(d0);   // row gID,   cols (tig*2, tig*2+1)
        float2 hi = h2f2(d1);   // row gID+8, same cols
        y[nt][0] = fmaf(xv0, lo.x, y[nt][0]);
        y[nt][1] = fmaf(xv0, lo.y, y[nt][1]);
        y[nt][2] = fmaf(xv1, hi.x, y[nt][2]);
        y[nt][3] = fmaf(xv1, hi.y, y[nt][3]);
    }
}

__global__ void __launch_bounds__(THREADS, 7)
metaLinear_kernel(const float* __restrict__ x1, const float* __restrict__ x2,
                  const float* __restrict__ bvec, float* __restrict__ out)
{
    extern __shared__ float x2s[];

    const int tid  = threadIdx.x;
    const int lane = tid & 31, wid = tid >> 5;
    const int gID = lane >> 2, tig = lane & 3;
    const int tok0 = blockIdx.x * TOK_TILE;
    const int cn = wid * 16;                      // 4 warps cover 64 cols

    // stage x2 tile (padded stride); the ONLY block barrier
    for (int i = tid; i < TOK_TILE * 64; i += THREADS) {
        int r = i >> 6, c = i & 63;
        x2s[r * X2_STRIDE + c] = x2[(size_t)(tok0 + r) * 64 + c];
    }

    uint32_t A[2][4];
    float y[2][4];
#pragma unroll
    for (int nt = 0; nt < 2; nt++)
#pragma unroll
        for (int j = 0; j < 4; j++) y[nt][j] = 0.0f;

    load_A(A, x1, tok0, 0, gID, tig);

    uint32_t bf0[2][4], bf1[2][4];
    load_frags(bf0, 0, cn, gID, tig);

    __syncthreads();   // x2s visible

    // free-running main loop, register double-buffered B fragments
    for (int s = 0; s < NSLICES; s += 2) {
        const int kb = s >> 6;
        const int c  = s & 63;

        load_frags(bf1, s + 1, cn, gID, tig);
        if (kb == 0)
            chunk_mma<true >(bf0, x2s, bvec, A, y, c, cn, gID, tig);
        else
            chunk_mma<false>(bf0, x2s, bvec, A, y, c, cn, gID, tig);

        int s2 = (s + 2 < NSLICES) ? s + 2 : NSLICES - 1;
        load_frags(bf0, s2, cn, gID, tig);
        if (kb == 0)
            chunk_mma<true >(bf1, x2s, bvec, A, y, c + 1, cn, gID, tig);
        else
            chunk_mma<false>(bf1, x2s, bvec, A, y, c + 1, cn, gID, tig);

        if (c == 62 && kb + 1 < KB_STEPS)
            load_A(A, x1, tok0, kb + 1, gID, tig);
    }

    // write y: rows tok0+gID and tok0+gID+8
#pragma unroll
    for (int h = 0; h < 2; h++) {
        int row = tok0 + gID + h * 8;
#pragma unroll
        for (int nt = 0; nt < 2; nt++) {
            float2 v;
            v.x = y[nt][h * 2 + 0];
            v.y = y[nt][h * 2 + 1];
            *reinterpret_cast<float2*>(
                out + (size_t)row * 64 + cn + nt * 8 + tig * 2) = v;
        }
    }
}

extern "C" void kernel_launch(void* const* d_in, const int* in_sizes, int n_in,
                              void* d_out, int out_size) {
    const float* x1   = (const float*)d_in[0];
    const float* x2   = (const float*)d_in[1];
    const float* W    = (const float*)d_in[2];
    const float* bvec = (const float*)d_in[3];
    float* out = (float*)d_out;
    (void)in_sizes; (void)n_in; (void)out_size;

    prep_kernel<<<2048, 256>>>(W);
    metaLinear_kernel<<<NUM_TILES, THREADS, SMEM_BYTES>>>(x1, x2, bvec, out);
}

// round 14
// speedup vs baseline: 1.7663x; 1.7663x over previous
#include <cuda_runtime.h>
#include <cuda_fp16.h>
#include <cstdint>

// ---------------- configuration ----------------
#define TOK_TILE     64
#define NUM_TILES    256          // 16384 / 64 -> 2 CTAs resident per SM
#define THREADS      256          // 8 warps: 2 m-groups x 4 n-groups (Mw=32, Nw=16)
#define KB_STEPS     8            // K=256 in blocks of 32
#define NSLICES      512
#define SLICE_WORDS  1024         // 64 o x 32 k halves = 1024 b32 words

// smem: x2 tile as duplicated-f16x2 (one u32 per (t,c))
#define X2D_STRIDE   65
#define SMEM_BYTES   (TOK_TILE * X2D_STRIDE * 4)   // 16640

// W slices (512 x 1024 words) + bias matrix (2 x 1024 words) fragment-ordered
__device__ uint32_t g_Wh[4096 * 128 + 2048];

static __device__ __forceinline__ uint32_t pack_h2(float lo, float hi) {
    uint32_t r;
    asm("cvt.rn.f16x2.f32 %0, %1, %2;" : "=r"(r) : "f"(hi), "f"(lo));
    return r;
}
static __device__ __forceinline__ uint32_t hmul2(uint32_t a, uint32_t b) {
    uint32_t r;
    asm("mul.rn.f16x2 %0, %1, %2;" : "=r"(r) : "r"(a), "r"(b));
    return r;
}
// D(f32x4) += A(f16)xB(f16)  -- accumulator never leaves the chain
static __device__ __forceinline__ void mma_acc(float& d0, float& d1, float& d2, float& d3,
                                               const uint32_t* a, uint32_t b0, uint32_t b1) {
    asm("mma.sync.aligned.m16n8k16.row.col.f32.f16.f16.f32 "
        "{%0,%1,%2,%3}, {%4,%5,%6,%7}, {%8,%9}, {%0,%1,%2,%3};"
        : "+f"(d0), "+f"(d1), "+f"(d2), "+f"(d3)
        : "r"(a[0]), "r"(a[1]), "r"(a[2]), "r"(a[3]), "r"(b0), "r"(b1));
}

// -------- W pre-transform: fp32 -> f16x2, fragment order (proven layout) --------
__global__ void prep_kernel(const float* __restrict__ W) {
    int idx = blockIdx.x * 256 + threadIdx.x;      // 524,288 threads
    int s   = idx >> 10;
    int rem = idx & 1023;
    int o   = rem >> 4;
    int r   = (rem >> 2) & 3;
    int q   = rem & 3;
    int ks  = q >> 1, hb = q & 1;
    int kb  = s >> 6, c = s & 63;
    const float* src = W + (size_t)(c * 64 + o) * 256 + kb * 32 + ks * 16 + hb * 8 + r * 2;
    g_Wh[idx] = pack_h2(src[0], src[1]);
}

// -------- bias matrix Bm[c][o] = bvec[c*64+o] as 2 fragment-ordered pseudo-slices --------
__global__ void prep_bias(const float* __restrict__ bvec) {
    int idx = threadIdx.x + blockIdx.x * 256;      // 2048 threads
    int kh  = idx >> 10;
    int rem = idx & 1023;
    int o   = rem >> 4;
    int r   = (rem >> 2) & 3;
    int q   = rem & 3;
    int ks  = q >> 1, hb = q & 1;
    int k0  = kh * 32 + ks * 16 + hb * 8 + r * 2;  // k0 = c index
    g_Wh[4096 * 128 + idx] = pack_h2(bvec[k0 * 64 + o], bvec[(k0 + 1) * 64 + o]);
}

// this warp's B fragments for slice s: 1 LDG.128 per nt, fully coalesced
static __device__ __forceinline__ void load_frags(uint32_t bf[2][4], int s,
                                                  int cn, int gID, int tig) {
    const uint4* base = reinterpret_cast<const uint4*>(g_Wh) + (size_t)s * (SLICE_WORDS / 4);
#pragma unroll
    for (int nt = 0; nt < 2; nt++) {
        int o = cn + nt * 8 + gID;
        uint4 v = __ldg(base + o * 4 + tig);
        bf[nt][0] = v.x; bf[nt][1] = v.y; bf[nt][2] = v.z; bf[nt][3] = v.w;
    }
}

// A fragments (src -> fp16) for one 32-wide k block; generic row stride
static __device__ __forceinline__ void load_A(uint32_t A[2][2][4],
                                              const float* __restrict__ src,
                                              int row0, int row_stride, int k_base,
                                              int rm, int gID, int tig) {
#pragma unroll
    for (int mt = 0; mt < 2; mt++) {
        const float* r0 = src + (size_t)(row0 + rm + mt * 16 + gID) * row_stride + k_base;
        const float* r1 = r0 + 8 * row_stride;
#pragma unroll
        for (int ks = 0; ks < 2; ks++) {
            int k0 = ks * 16 + tig * 2;
            float2 a0 = *reinterpret_cast<const float2*>(r0 + k0);
            float2 a1 = *reinterpret_cast<const float2*>(r1 + k0);
            float2 a2 = *reinterpret_cast<const float2*>(r0 + k0 + 8);
            float2 a3 = *reinterpret_cast<const float2*>(r1 + k0 + 8);
            A[mt][ks][0] = pack_h2(a0.x, a0.y);
            A[mt][ks][1] = pack_h2(a1.x, a1.y);
            A[mt][ks][2] = pack_h2(a2.x, a2.y);
            A[mt][ks][3] = pack_h2(a3.x, a3.y);
        }
    }
}

// one chunk: scale A by x2[t,c] (fma pipe) then 8 HMMA into persistent f32 D
static __device__ __forceinline__ void chunk_mma(
    const uint32_t bf[2][4], const uint32_t* __restrict__ x2ds,
    const uint32_t A[2][2][4], float D[2][2][4],
    int c, int rm, int gID)
{
#pragma unroll
    for (int mt = 0; mt < 2; mt++) {
        uint32_t xq0 = x2ds[(rm + mt * 16 + gID) * X2D_STRIDE + c];
        uint32_t xq1 = x2ds[(rm + mt * 16 + gID + 8) * X2D_STRIDE + c];
        uint32_t Ap[2][4];
#pragma unroll
        for (int ks = 0; ks < 2; ks++) {
            Ap[ks][0] = hmul2(A[mt][ks][0], xq0);
            Ap[ks][1] = hmul2(A[mt][ks][1], xq1);
            Ap[ks][2] = hmul2(A[mt][ks][2], xq0);
            Ap[ks][3] = hmul2(A[mt][ks][3], xq1);
        }
#pragma unroll
        for (int nt = 0; nt < 2; nt++) {
            mma_acc(D[mt][nt][0], D[mt][nt][1], D[mt][nt][2], D[mt][nt][3],
                    Ap[0], bf[nt][0], bf[nt][1]);
            mma_acc(D[mt][nt][0], D[mt][nt][1], D[mt][nt][2], D[mt][nt][3],
                    Ap[1], bf[nt][2], bf[nt][3]);
        }
    }
}

__global__ void __launch_bounds__(THREADS, 2)
metaLinear_kernel(const float* __restrict__ x1, const float* __restrict__ x2,
                  float* __restrict__ out)
{
    extern __shared__ uint32_t x2ds[];

    const int tid  = threadIdx.x;
    const int lane = tid & 31, wid = tid >> 5;
    const int wm = wid >> 2, wn = wid & 3;          // 2 m-groups x 4 n-groups
    const int gID = lane >> 2, tig = lane & 3;
    const int tok0 = blockIdx.x * TOK_TILE;
    const int rm = wm * 32;
    const int cn = wn * 16;

    // x2 tile -> smem as duplicated f16x2; the ONLY block barrier
    for (int i = tid; i < TOK_TILE * 64; i += THREADS) {
        int r = i >> 6, c = i & 63;
        float v = x2[(size_t)(tok0 + r) * 64 + c];
        x2ds[r * X2D_STRIDE + c] = pack_h2(v, v);
    }

    uint32_t A[2][2][4];
    float D[2][2][4];
#pragma unroll
    for (int mt = 0; mt < 2; mt++)
#pragma unroll
        for (int nt = 0; nt < 2; nt++)
#pragma unroll
            for (int j = 0; j < 4; j++) D[mt][nt][j] = 0.0f;

    load_A(A, x1, tok0, 256, 0, rm, gID, tig);

    uint32_t bf0[2][4], bf1[2][4];
    load_frags(bf0, 0, cn, gID, tig);

    __syncthreads();   // x2ds visible

    // free-running main loop: accumulators never read -> no pipeline drains
    for (int s = 0; s < NSLICES; s += 2) {
        const int kb = s >> 6;
        const int c  = s & 63;

        load_frags(bf1, s + 1, cn, gID, tig);
        chunk_mma(bf0, x2ds, A, D, c, rm, gID);

        int s2 = (s + 2 < NSLICES) ? s + 2 : NSLICES - 1;
        load_frags(bf0, s2, cn, gID, tig);
        chunk_mma(bf1, x2ds, A, D, c + 1, rm, gID);

        if (c == 62 && kb + 1 < KB_STEPS)
            load_A(A, x1, tok0, 256, (kb + 1) * 32, rm, gID, tig);
    }

    // bias: y += x2 . Bm  (two k32 pseudo-chunks, A = x2 fragments, no scaling)
#pragma unroll
    for (int kh = 0; kh < 2; kh++) {
        uint32_t Ab[2][2][4];
        load_A(Ab, x2, tok0, 64, kh * 32, rm, gID, tig);
        uint32_t bfb[2][4];
        load_frags(bfb, 512 + kh, cn, gID, tig);
#pragma unroll
        for (int mt = 0; mt < 2; mt++)
#pragma unroll
            for (int nt = 0; nt < 2; nt++) {
                mma_acc(D[mt][nt][0], D[mt][nt][1], D[mt][nt][2], D[mt][nt][3],
                        Ab[mt][0], bfb[nt][0], bfb[nt][1]);
                mma_acc(D[mt][nt][0], D[mt][nt][1], D[mt][nt][2], D[mt][nt][3],
                        Ab[mt][1], bfb[nt][2], bfb[nt][3]);
            }
    }

    // write y: d0,d1 = row gID cols (tig*2, tig*2+1); d2,d3 = row gID+8
#pragma unroll
    for (int mt = 0; mt < 2; mt++)
#pragma unroll
        for (int h = 0; h < 2; h++) {
            int row = tok0 + rm + mt * 16 + gID + h * 8;
#pragma unroll
            for (int nt = 0; nt < 2; nt++) {
                float2 v;
                v.x = D[mt][nt][h * 2 + 0];
                v.y = D[mt][nt][h * 2 + 1];
                *reinterpret_cast<float2*>(
                    out + (size_t)row * 64 + cn + nt * 8 + tig * 2) = v;
            }
        }
}

extern "C" void kernel_launch(void* const* d_in, const int* in_sizes, int n_in,
                              void* d_out, int out_size) {
    const float* x1   = (const float*)d_in[0];
    const float* x2   = (const float*)d_in[1];
    const float* W    = (const float*)d_in[2];
    const float* bvec = (const float*)d_in[3];
    float* out = (float*)d_out;
    (void)in_sizes; (void)n_in; (void)out_size;

    prep_kernel<<<2048, 256>>>(W);
    prep_bias<<<8, 256>>>(bvec);
    metaLinear_kernel<<<NUM_TILES, THREADS, SMEM_BYTES>>>(x1, x2, out);
}